// round 1
// baseline (speedup 1.0000x reference)
#include <cuda_runtime.h>
#include <cstdint>

#define EMBED 1024
#define HEADS 16
#define HDIM  64
#define BATCH 4
#define SEQ   1023
#define MROWS (BATCH*SEQ)      /* 4092 */
#define NQKV  (3*EMBED)        /* 3072 */

// ---------------- scratch (static device globals: allocation-free) ----------
__device__ float g_qkv [BATCH*SEQ*NQKV];   // ~50.3 MB: q|k|v per token
__device__ float g_kimg[BATCH*EMBED];
__device__ float g_vimg[BATCH*EMBED];
__device__ float g_attn[BATCH*SEQ*EMBED];  // ~16.8 MB attention output

// ---------------- generic SGEMM: C = A(MxK,row) @ B(KxN,row) + bias --------
template<int BM, int BN, int BK, int TM, int TN>
__global__ __launch_bounds__(256)
void sgemm_bias(const float* __restrict__ A, const float* __restrict__ Bm,
                const float* __restrict__ bias, float* __restrict__ C,
                int M, int N, int K)
{
    __shared__ float As[BK][BM + 4];
    __shared__ float Bs[BK][BN];

    const int tid = threadIdx.x;
    const int rowBase = blockIdx.y * BM;
    const int colBase = blockIdx.x * BN;

    // A tile load mapping: 128x8 floats, 256 threads, one float4 each
    const int aRow = tid >> 1;          // 0..127
    const int aCol = (tid & 1) * 4;     // 0 or 4
    // B tile load mapping: 8x128 floats, one float4 each
    const int bRow = tid >> 5;          // 0..7
    const int bCol = (tid & 31) * 4;    // 0..124

    const int ty = tid >> 4;            // 0..15
    const int tx = tid & 15;            // 0..15

    float acc[TM][TN];
    #pragma unroll
    for (int i = 0; i < TM; i++)
        #pragma unroll
        for (int j = 0; j < TN; j++) acc[i][j] = 0.f;

    for (int k0 = 0; k0 < K; k0 += BK) {
        // load A tile (transposed into smem)
        float4 av;
        const int gr = rowBase + aRow;
        if (gr < M) av = *reinterpret_cast<const float4*>(&A[(size_t)gr * K + k0 + aCol]);
        else        av = make_float4(0.f, 0.f, 0.f, 0.f);
        As[aCol + 0][aRow] = av.x;
        As[aCol + 1][aRow] = av.y;
        As[aCol + 2][aRow] = av.z;
        As[aCol + 3][aRow] = av.w;
        // load B tile
        *reinterpret_cast<float4*>(&Bs[bRow][bCol]) =
            *reinterpret_cast<const float4*>(&Bm[(size_t)(k0 + bRow) * N + colBase + bCol]);
        __syncthreads();

        #pragma unroll
        for (int k = 0; k < BK; k++) {
            float regM[TM], regN[TN];
            *reinterpret_cast<float4*>(&regM[0]) = *reinterpret_cast<const float4*>(&As[k][ty * TM]);
            *reinterpret_cast<float4*>(&regM[4]) = *reinterpret_cast<const float4*>(&As[k][ty * TM + 4]);
            *reinterpret_cast<float4*>(&regN[0]) = *reinterpret_cast<const float4*>(&Bs[k][tx * TN]);
            *reinterpret_cast<float4*>(&regN[4]) = *reinterpret_cast<const float4*>(&Bs[k][tx * TN + 4]);
            #pragma unroll
            for (int i = 0; i < TM; i++)
                #pragma unroll
                for (int j = 0; j < TN; j++)
                    acc[i][j] += regM[i] * regN[j];
        }
        __syncthreads();
    }

    #pragma unroll
    for (int i = 0; i < TM; i++) {
        const int r = rowBase + ty * TM + i;
        if (r >= M) continue;
        #pragma unroll
        for (int j = 0; j < TN; j += 4) {
            const int c = colBase + tx * TN + j;
            float4 o;
            o.x = acc[i][j + 0] + bias[c + 0];
            o.y = acc[i][j + 1] + bias[c + 1];
            o.z = acc[i][j + 2] + bias[c + 2];
            o.w = acc[i][j + 3] + bias[c + 3];
            *reinterpret_cast<float4*>(&C[(size_t)r * N + c]) = o;
        }
    }
}

// ---------------- image K/V: k_img[b,n] = img[b,:] . uk_w[n,:] + uk_b[n] ----
__global__ __launch_bounds__(256)
void img_kv_kernel(const float* __restrict__ img,
                   const float* __restrict__ uk_w, const float* __restrict__ uk_b,
                   const float* __restrict__ uv_w, const float* __restrict__ uv_b,
                   float* __restrict__ kimg, float* __restrict__ vimg)
{
    const int w    = (blockIdx.x * blockDim.x + threadIdx.x) >> 5;  // global warp id
    const int lane = threadIdx.x & 31;
    // 8192 outputs total: [which(2)][b(4)][n(1024)]
    const int which = w >> 12;
    const int rem   = w & 4095;
    const int b     = rem >> 10;
    const int n     = rem & 1023;

    const float* W    = which ? uv_w : uk_w;
    const float* bias = which ? uv_b : uk_b;
    const float* x    = img + b * EMBED;
    const float* wr   = W + (size_t)n * EMBED;

    float s = 0.f;
    #pragma unroll 4
    for (int e = lane * 4; e < EMBED; e += 128) {
        float4 xv = *reinterpret_cast<const float4*>(x + e);
        float4 wv = *reinterpret_cast<const float4*>(wr + e);
        s += xv.x * wv.x + xv.y * wv.y + xv.z * wv.z + xv.w * wv.w;
    }
    #pragma unroll
    for (int o = 16; o; o >>= 1) s += __shfl_xor_sync(0xffffffffu, s, o);
    if (lane == 0) {
        const float v = s + bias[n];
        if (which) vimg[b * EMBED + n] = v;
        else       kimg[b * EMBED + n] = v;
    }
}

// ---------------- flash attention: one query per thread --------------------
// keys: kj=0 -> image K/V; kj>=1 -> word key kj-1. Visible iff kj <= qi+1.
// mask add for word keys: attention_mask[b, kj-1]; image key gets 0.
#define ATT_QB 128
#define ATT_TK 64

__global__ __launch_bounds__(128)
void attn_kernel(const float* __restrict__ qkv,
                 const float* __restrict__ kimg, const float* __restrict__ vimg,
                 const float* __restrict__ mask, float* __restrict__ out)
{
    __shared__ float Ks[ATT_TK][HDIM + 4];
    __shared__ float Vs[ATT_TK][HDIM + 4];
    __shared__ float Ms[ATT_TK];

    const int bh = blockIdx.y;
    const int b  = bh >> 4;
    const int h  = bh & 15;
    const int q0 = blockIdx.x * ATT_QB;
    const int tid = threadIdx.x;
    const int qi  = q0 + tid;
    const bool active = (qi < SEQ);
    const int qc = active ? qi : (SEQ - 1);

    float q[HDIM];
    {
        const float* qp = qkv + (size_t)(b * SEQ + qc) * NQKV + h * HDIM;
        #pragma unroll
        for (int d = 0; d < HDIM; d += 4) {
            float4 v = *reinterpret_cast<const float4*>(qp + d);
            q[d + 0] = v.x * 0.125f;   // pre-apply 1/sqrt(HDIM)
            q[d + 1] = v.y * 0.125f;
            q[d + 2] = v.z * 0.125f;
            q[d + 3] = v.w * 0.125f;
        }
    }

    float acc[HDIM];
    #pragma unroll
    for (int d = 0; d < HDIM; d++) acc[d] = 0.f;
    float mrun = -1e30f, l = 0.f;

    const int qe     = min(q0 + ATT_QB, SEQ) - 1;   // last query in block
    const int kcount = qe + 2;                      // keys 0..qe+1
    const int ntiles = (kcount + ATT_TK - 1) / ATT_TK;

    for (int t = 0; t < ntiles; t++) {
        const int kbase = t * ATT_TK;
        __syncthreads();
        {
            const int r  = tid >> 1;          // 0..63
            const int c0 = (tid & 1) * 32;
            const int kj = kbase + r;
            const float *ksrc, *vsrc;
            if (kj == 0) {
                ksrc = kimg + b * EMBED + h * HDIM;
                vsrc = vimg + b * EMBED + h * HDIM;
            } else {
                const int j = min(kj, SEQ) - 1;    // clamp OOB (masked later)
                ksrc = qkv + (size_t)(b * SEQ + j) * NQKV + EMBED + h * HDIM;
                vsrc = ksrc + EMBED;
            }
            #pragma unroll
            for (int i = 0; i < 8; i++) {
                const int c = c0 + i * 4;
                *reinterpret_cast<float4*>(&Ks[r][c]) = *reinterpret_cast<const float4*>(ksrc + c);
                *reinterpret_cast<float4*>(&Vs[r][c]) = *reinterpret_cast<const float4*>(vsrc + c);
            }
            if ((tid & 1) == 0)
                Ms[r] = (kj > 0 && kj <= SEQ) ? mask[b * SEQ + (kj - 1)] : 0.f;
        }
        __syncthreads();

        const int klim = min(ATT_TK, kcount - kbase);
        for (int kk = 0; kk < klim; kk++) {
            const int kj = kbase + kk;
            if (kj > qi + 1) break;          // causal: later keys all invisible too
            float s = 0.f;
            #pragma unroll
            for (int d = 0; d < HDIM; d += 4) {
                float4 kv = *reinterpret_cast<const float4*>(&Ks[kk][d]);
                s += q[d] * kv.x + q[d + 1] * kv.y + q[d + 2] * kv.z + q[d + 3] * kv.w;
            }
            s += Ms[kk];
            if (s > mrun) {                  // rare (~ln K per query): lazy rescale
                const float cfac = __expf(mrun - s);
                l = l * cfac + 1.f;
                #pragma unroll
                for (int d = 0; d < HDIM; d += 4) {
                    float4 vv = *reinterpret_cast<const float4*>(&Vs[kk][d]);
                    acc[d + 0] = acc[d + 0] * cfac + vv.x;
                    acc[d + 1] = acc[d + 1] * cfac + vv.y;
                    acc[d + 2] = acc[d + 2] * cfac + vv.z;
                    acc[d + 3] = acc[d + 3] * cfac + vv.w;
                }
                mrun = s;
            } else {
                const float p = __expf(s - mrun);
                l += p;
                #pragma unroll
                for (int d = 0; d < HDIM; d += 4) {
                    float4 vv = *reinterpret_cast<const float4*>(&Vs[kk][d]);
                    acc[d + 0] += p * vv.x;
                    acc[d + 1] += p * vv.y;
                    acc[d + 2] += p * vv.z;
                    acc[d + 3] += p * vv.w;
                }
            }
        }
    }

    if (active) {
        const float inv = 1.f / l;
        float* op = out + (size_t)(b * SEQ + qi) * EMBED + h * HDIM;
        #pragma unroll
        for (int d = 0; d < HDIM; d += 4) {
            float4 o;
            o.x = acc[d + 0] * inv;
            o.y = acc[d + 1] * inv;
            o.z = acc[d + 2] * inv;
            o.w = acc[d + 3] * inv;
            *reinterpret_cast<float4*>(op + d) = o;
        }
    }
}

// ---------------- launcher --------------------------------------------------
extern "C" void kernel_launch(void* const* d_in, const int* in_sizes, int n_in,
                              void* d_out, int out_size)
{
    const float* word   = (const float*)d_in[0];   // (4,1023,1024)
    const float* img    = (const float*)d_in[1];   // (4,1024)
    const float* amask  = (const float*)d_in[2];   // (4,1,1,1023)
    const float* attn_w = (const float*)d_in[3];   // (1024,3072)
    const float* attn_b = (const float*)d_in[4];   // (3072,)
    const float* proj_w = (const float*)d_in[5];   // (1024,1024)
    const float* proj_b = (const float*)d_in[6];   // (1024,)
    const float* uk_w   = (const float*)d_in[7];   // (1024,1024)
    const float* uk_b   = (const float*)d_in[8];
    const float* uv_w   = (const float*)d_in[9];
    const float* uv_b   = (const float*)d_in[10];
    float* out = (float*)d_out;

    void *p_qkv, *p_kimg, *p_vimg, *p_attn;
    cudaGetSymbolAddress(&p_qkv,  g_qkv);
    cudaGetSymbolAddress(&p_kimg, g_kimg);
    cudaGetSymbolAddress(&p_vimg, g_vimg);
    cudaGetSymbolAddress(&p_attn, g_attn);
    float* qkv  = (float*)p_qkv;
    float* kimg = (float*)p_kimg;
    float* vimg = (float*)p_vimg;
    float* attn = (float*)p_attn;

    // 1) QKV projection: (4092 x 1024) @ (1024 x 3072) + b
    {
        dim3 grid(NQKV / 128, (MROWS + 127) / 128);
        sgemm_bias<128, 128, 8, 8, 8><<<grid, 256>>>(word, attn_w, attn_b, qkv,
                                                     MROWS, NQKV, EMBED);
    }
    // 2) image K/V GEMV (independent of 1; same stream serializes, fine)
    img_kv_kernel<<<1024, 256>>>(img, uk_w, uk_b, uv_w, uv_b, kimg, vimg);

    // 3) attention
    {
        dim3 grid((SEQ + ATT_QB - 1) / ATT_QB, BATCH * HEADS);
        attn_kernel<<<grid, ATT_QB>>>(qkv, kimg, vimg, amask, attn);
    }
    // 4) output projection: (4092 x 1024) @ (1024 x 1024) + b
    {
        dim3 grid(EMBED / 128, (MROWS + 127) / 128);
        sgemm_bias<128, 128, 8, 8, 8><<<grid, 256>>>(attn, proj_w, proj_b, out,
                                                     MROWS, EMBED, EMBED);
    }
}

// round 3
// speedup vs baseline: 1.4890x; 1.4890x over previous
#include <cuda_runtime.h>
#include <cuda_bf16.h>
#include <cstdint>

#define EMBED 1024
#define HEADS 16
#define HDIM  64
#define BATCH 4
#define SEQ   1023
#define MROWS (BATCH*SEQ)      /* 4092 */
#define NQKV  (3*EMBED)        /* 3072 */

// ===================== scratch (static device globals) =====================
__device__ float g_qkv [BATCH*SEQ*NQKV];      // 50.3 MB
__device__ float g_kimg[BATCH*EMBED];
__device__ float g_vimg[BATCH*EMBED];
__device__ float g_attn[BATCH*SEQ*EMBED];     // 16.8 MB
__device__ __nv_bfloat16 g_Ahi[4096*1024];    // split activations (reused)
__device__ __nv_bfloat16 g_Alo[4096*1024];
__device__ __nv_bfloat16 g_Whi[NQKV*EMBED];   // qkv weight, transposed [N][K]
__device__ __nv_bfloat16 g_Wlo[NQKV*EMBED];
__device__ __nv_bfloat16 g_Phi[EMBED*EMBED];  // proj weight, transposed
__device__ __nv_bfloat16 g_Plo[EMBED*EMBED];

// ===================== small helpers =======================================
__device__ __forceinline__ uint32_t smem_to_u32(const void* p) {
    uint32_t a;
    asm("{ .reg .u64 t; cvta.to.shared.u64 t, %1; cvt.u32.u64 %0, t; }" : "=r"(a) : "l"(p));
    return a;
}
__device__ __forceinline__ void ldsm4(uint32_t (&r)[4], uint32_t addr) {
    asm volatile("ldmatrix.sync.aligned.m8n8.x4.shared.b16 {%0,%1,%2,%3}, [%4];"
        : "=r"(r[0]), "=r"(r[1]), "=r"(r[2]), "=r"(r[3]) : "r"(addr));
}
__device__ __forceinline__ void mma16816(float (&c)[4], const uint32_t (&a)[4],
                                         uint32_t b0, uint32_t b1) {
    asm volatile("mma.sync.aligned.m16n8k16.row.col.f32.bf16.bf16.f32 "
        "{%0,%1,%2,%3}, {%4,%5,%6,%7}, {%8,%9}, {%0,%1,%2,%3};"
        : "+f"(c[0]), "+f"(c[1]), "+f"(c[2]), "+f"(c[3])
        : "r"(a[0]), "r"(a[1]), "r"(a[2]), "r"(a[3]), "r"(b0), "r"(b1));
}

// ===================== conversion kernels ==================================
__global__ __launch_bounds__(256)
void conv_split(const float* __restrict__ in, __nv_bfloat16* __restrict__ hi,
                __nv_bfloat16* __restrict__ lo, int n4)
{
    int i = blockIdx.x * blockDim.x + threadIdx.x;
    if (i >= n4) return;
    float4 v = reinterpret_cast<const float4*>(in)[i];
    __nv_bfloat16 hx = __float2bfloat16_rn(v.x);
    __nv_bfloat16 hy = __float2bfloat16_rn(v.y);
    __nv_bfloat16 hz = __float2bfloat16_rn(v.z);
    __nv_bfloat16 hw = __float2bfloat16_rn(v.w);
    __nv_bfloat162* h2 = reinterpret_cast<__nv_bfloat162*>(hi) + i * 2;
    __nv_bfloat162* l2 = reinterpret_cast<__nv_bfloat162*>(lo) + i * 2;
    h2[0] = __nv_bfloat162(hx, hy);
    h2[1] = __nv_bfloat162(hz, hw);
    l2[0] = __nv_bfloat162(__float2bfloat16_rn(v.x - __bfloat162float(hx)),
                           __float2bfloat16_rn(v.y - __bfloat162float(hy)));
    l2[1] = __nv_bfloat162(__float2bfloat16_rn(v.z - __bfloat162float(hz)),
                           __float2bfloat16_rn(v.w - __bfloat162float(hw)));
}

// fp32 W[K][N] row-major -> bf16 split, transposed: out[n][k]
__global__ __launch_bounds__(256)
void conv_split_T(const float* __restrict__ W, __nv_bfloat16* __restrict__ hi,
                  __nv_bfloat16* __restrict__ lo, int K, int N)
{
    __shared__ float t[32][33];
    int n0 = blockIdx.x * 32, k0 = blockIdx.y * 32;
    int tx = threadIdx.x, ty = threadIdx.y;      // block (32, 8)
    #pragma unroll
    for (int i = 0; i < 32; i += 8)
        t[ty + i][tx] = W[(size_t)(k0 + ty + i) * N + n0 + tx];
    __syncthreads();
    #pragma unroll
    for (int i = 0; i < 32; i += 8) {
        float v = t[tx][ty + i];
        __nv_bfloat16 h = __float2bfloat16_rn(v);
        size_t o = (size_t)(n0 + ty + i) * K + k0 + tx;
        hi[o] = h;
        lo[o] = __float2bfloat16_rn(v - __bfloat162float(h));
    }
}

// ===================== HMMA bf16x3 GEMM ====================================
// C[M,N] = A @ B^T + bias;  A split (Ahi/Alo [M][1024]), B split ([N][1024]).
// Block 128x128x32, 256 threads (8 warps of 32x64), cp.async double buffer.
#define BKC    32
#define NCHU   (EMBED / BKC)          /* 32 */
#define TPAD   40                     /* 32 + 8 pad -> 80B rows, conflict-free */
#define TILE_E (128 * TPAD)           /* 5120 elems per array tile */
#define STAGE_B (4 * TILE_E * 2)      /* 40960 bytes per stage */
#define GEMM_SMEM_B (2 * STAGE_B)     /* 81920 bytes */

__global__ __launch_bounds__(256, 2)
void gemm_mma3(const __nv_bfloat16* __restrict__ Ahi, const __nv_bfloat16* __restrict__ Alo,
               const __nv_bfloat16* __restrict__ Bhi, const __nv_bfloat16* __restrict__ Blo,
               const float* __restrict__ bias, float* __restrict__ C, int M, int N)
{
    extern __shared__ __nv_bfloat16 sm[];
    const uint32_t smb = smem_to_u32(sm);
    const int tid  = threadIdx.x;
    const int wid  = tid >> 5, lane = tid & 31;
    const int wm   = wid & 3,  wn   = wid >> 2;
    const int rowBase = blockIdx.y * 128, colBase = blockIdx.x * 128;

    // cp.async mapping: thread -> (row lr, k-offset lk), 16B each, 2 row-waves
    const int lr = tid >> 2;           // 0..63
    const int lk = (tid & 3) * 8;      // 0,8,16,24
    const __nv_bfloat16* gsrc[4];
    gsrc[0] = Ahi + (size_t)(rowBase + lr) * EMBED + lk;
    gsrc[1] = Alo + (size_t)(rowBase + lr) * EMBED + lk;
    gsrc[2] = Bhi + (size_t)(colBase + lr) * EMBED + lk;
    gsrc[3] = Blo + (size_t)(colBase + lr) * EMBED + lk;
    const uint32_t sdst0 = smb + (uint32_t)(lr * TPAD + lk) * 2;

    auto issue = [&](int ch) {
        const uint32_t sb = sdst0 + (uint32_t)(ch & 1) * STAGE_B;
        #pragma unroll
        for (int w = 0; w < 4; w++) {
            const __nv_bfloat16* g = gsrc[w] + ch * BKC;
            const uint32_t d = sb + (uint32_t)w * (TILE_E * 2);
            asm volatile("cp.async.cg.shared.global [%0], [%1], 16;"
                         :: "r"(d), "l"(g));
            asm volatile("cp.async.cg.shared.global [%0], [%1], 16;"
                         :: "r"(d + 64 * TPAD * 2), "l"(g + (size_t)64 * EMBED));
        }
        asm volatile("cp.async.commit_group;");
    };

    float acc[2][8][4] = {};

    const int lrow  = lane & 15;
    const int lcol8 = (lane >> 4) * 8;

    issue(0);
    for (int ch = 0; ch < NCHU; ch++) {
        const int s = ch & 1;
        if (ch + 1 < NCHU) { issue(ch + 1); asm volatile("cp.async.wait_group 1;"); }
        else               { asm volatile("cp.async.wait_group 0;"); }
        __syncthreads();

        const uint32_t stb  = smb + (uint32_t)s * STAGE_B;
        const uint32_t aoff = stb + (uint32_t)((wm * 32 + lrow) * TPAD + lcol8) * 2;
        const uint32_t boff = stb + 2u * (TILE_E * 2)
                            + (uint32_t)((wn * 64 + lrow) * TPAD + lcol8) * 2;
        #pragma unroll
        for (int kk = 0; kk < BKC; kk += 16) {
            uint32_t ah[2][4], al[2][4];
            #pragma unroll
            for (int mt = 0; mt < 2; mt++) {
                ldsm4(ah[mt], aoff + (uint32_t)(mt * 16 * TPAD + kk) * 2);
                ldsm4(al[mt], aoff + (TILE_E * 2) + (uint32_t)(mt * 16 * TPAD + kk) * 2);
            }
            #pragma unroll
            for (int np = 0; np < 4; np++) {
                uint32_t bh[4], bl[4];
                ldsm4(bh, boff + (uint32_t)(np * 16 * TPAD + kk) * 2);
                ldsm4(bl, boff + (TILE_E * 2) + (uint32_t)(np * 16 * TPAD + kk) * 2);
                #pragma unroll
                for (int mt = 0; mt < 2; mt++) {
                    mma16816(acc[mt][np * 2 + 0], ah[mt], bh[0], bh[2]);
                    mma16816(acc[mt][np * 2 + 1], ah[mt], bh[1], bh[3]);
                    mma16816(acc[mt][np * 2 + 0], ah[mt], bl[0], bl[2]);
                    mma16816(acc[mt][np * 2 + 1], ah[mt], bl[1], bl[3]);
                    mma16816(acc[mt][np * 2 + 0], al[mt], bh[0], bh[2]);
                    mma16816(acc[mt][np * 2 + 1], al[mt], bh[1], bh[3]);
                }
            }
        }
        __syncthreads();
    }

    // epilogue: c0,c1 -> (row g, col 2j), c2,c3 -> (row g+8)
    const int erow = lane >> 2;
    const int ecol = (lane & 3) * 2;
    #pragma unroll
    for (int mt = 0; mt < 2; mt++) {
        #pragma unroll
        for (int nt = 0; nt < 8; nt++) {
            const int col = colBase + wn * 64 + nt * 8 + ecol;
            const float bx = bias[col], by = bias[col + 1];
            const int r0 = rowBase + wm * 32 + mt * 16 + erow;
            if (r0 < M) {
                float2 v; v.x = acc[mt][nt][0] + bx; v.y = acc[mt][nt][1] + by;
                *reinterpret_cast<float2*>(&C[(size_t)r0 * N + col]) = v;
            }
            const int r1 = r0 + 8;
            if (r1 < M) {
                float2 v; v.x = acc[mt][nt][2] + bx; v.y = acc[mt][nt][3] + by;
                *reinterpret_cast<float2*>(&C[(size_t)r1 * N + col]) = v;
            }
        }
    }
}

// ===================== image K/V GEMV ======================================
__global__ __launch_bounds__(256)
void img_kv_kernel(const float* __restrict__ img,
                   const float* __restrict__ uk_w, const float* __restrict__ uk_b,
                   const float* __restrict__ uv_w, const float* __restrict__ uv_b,
                   float* __restrict__ kimg, float* __restrict__ vimg)
{
    const int w    = (blockIdx.x * blockDim.x + threadIdx.x) >> 5;
    const int lane = threadIdx.x & 31;
    const int which = w >> 12;
    const int rem   = w & 4095;
    const int b     = rem >> 10;
    const int n     = rem & 1023;

    const float* W    = which ? uv_w : uk_w;
    const float* bias = which ? uv_b : uk_b;
    const float* x    = img + b * EMBED;
    const float* wr   = W + (size_t)n * EMBED;

    float s = 0.f;
    #pragma unroll 4
    for (int e = lane * 4; e < EMBED; e += 128) {
        float4 xv = *reinterpret_cast<const float4*>(x + e);
        float4 wv = *reinterpret_cast<const float4*>(wr + e);
        s += xv.x * wv.x + xv.y * wv.y + xv.z * wv.z + xv.w * wv.w;
    }
    #pragma unroll
    for (int o = 16; o; o >>= 1) s += __shfl_xor_sync(0xffffffffu, s, o);
    if (lane == 0) {
        const float v = s + bias[n];
        if (which) vimg[b * EMBED + n] = v;
        else       kimg[b * EMBED + n] = v;
    }
}

// ===================== flash attention (fp32) ==============================
#define ATT_QB 128
#define ATT_TK 64

__global__ __launch_bounds__(128)
void attn_kernel(const float* __restrict__ qkv,
                 const float* __restrict__ kimg, const float* __restrict__ vimg,
                 const float* __restrict__ mask, float* __restrict__ out)
{
    __shared__ float Ks[ATT_TK][HDIM + 4];
    __shared__ float Vs[ATT_TK][HDIM + 4];
    __shared__ float Ms[ATT_TK];

    const int bh = blockIdx.y;
    const int b  = bh >> 4;
    const int h  = bh & 15;
    const int q0 = blockIdx.x * ATT_QB;
    const int tid = threadIdx.x;
    const int qi  = q0 + tid;
    const bool active = (qi < SEQ);
    const int qc = active ? qi : (SEQ - 1);

    float q[HDIM];
    {
        const float* qp = qkv + (size_t)(b * SEQ + qc) * NQKV + h * HDIM;
        #pragma unroll
        for (int d = 0; d < HDIM; d += 4) {
            float4 v = *reinterpret_cast<const float4*>(qp + d);
            q[d + 0] = v.x * 0.125f;
            q[d + 1] = v.y * 0.125f;
            q[d + 2] = v.z * 0.125f;
            q[d + 3] = v.w * 0.125f;
        }
    }

    float acc[HDIM];
    #pragma unroll
    for (int d = 0; d < HDIM; d++) acc[d] = 0.f;
    float mrun = -1e30f, l = 0.f;

    const int qe     = min(q0 + ATT_QB, SEQ) - 1;
    const int kcount = qe + 2;
    const int ntiles = (kcount + ATT_TK - 1) / ATT_TK;

    for (int t = 0; t < ntiles; t++) {
        const int kbase = t * ATT_TK;
        __syncthreads();
        {
            const int r  = tid >> 1;
            const int c0 = (tid & 1) * 32;
            const int kj = kbase + r;
            const float *ksrc, *vsrc;
            if (kj == 0) {
                ksrc = kimg + b * EMBED + h * HDIM;
                vsrc = vimg + b * EMBED + h * HDIM;
            } else {
                const int jj = min(kj, SEQ) - 1;
                ksrc = qkv + (size_t)(b * SEQ + jj) * NQKV + EMBED + h * HDIM;
                vsrc = ksrc + EMBED;
            }
            #pragma unroll
            for (int i = 0; i < 8; i++) {
                const int c = c0 + i * 4;
                *reinterpret_cast<float4*>(&Ks[r][c]) = *reinterpret_cast<const float4*>(ksrc + c);
                *reinterpret_cast<float4*>(&Vs[r][c]) = *reinterpret_cast<const float4*>(vsrc + c);
            }
            if ((tid & 1) == 0)
                Ms[r] = (kj > 0 && kj <= SEQ) ? mask[b * SEQ + (kj - 1)] : 0.f;
        }
        __syncthreads();

        const int klim = min(ATT_TK, kcount - kbase);
        for (int kk = 0; kk < klim; kk++) {
            const int kj = kbase + kk;
            if (kj > qi + 1) break;
            float s = 0.f;
            #pragma unroll
            for (int d = 0; d < HDIM; d += 4) {
                float4 kv = *reinterpret_cast<const float4*>(&Ks[kk][d]);
                s += q[d] * kv.x + q[d + 1] * kv.y + q[d + 2] * kv.z + q[d + 3] * kv.w;
            }
            s += Ms[kk];
            if (s > mrun) {
                const float cfac = __expf(mrun - s);
                l = l * cfac + 1.f;
                #pragma unroll
                for (int d = 0; d < HDIM; d += 4) {
                    float4 vv = *reinterpret_cast<const float4*>(&Vs[kk][d]);
                    acc[d + 0] = acc[d + 0] * cfac + vv.x;
                    acc[d + 1] = acc[d + 1] * cfac + vv.y;
                    acc[d + 2] = acc[d + 2] * cfac + vv.z;
                    acc[d + 3] = acc[d + 3] * cfac + vv.w;
                }
                mrun = s;
            } else {
                const float p = __expf(s - mrun);
                l += p;
                #pragma unroll
                for (int d = 0; d < HDIM; d += 4) {
                    float4 vv = *reinterpret_cast<const float4*>(&Vs[kk][d]);
                    acc[d + 0] += p * vv.x;
                    acc[d + 1] += p * vv.y;
                    acc[d + 2] += p * vv.z;
                    acc[d + 3] += p * vv.w;
                }
            }
        }
    }

    if (active) {
        const float inv = 1.f / l;
        float* op = out + (size_t)(b * SEQ + qi) * EMBED + h * HDIM;
        #pragma unroll
        for (int d = 0; d < HDIM; d += 4) {
            float4 o;
            o.x = acc[d + 0] * inv;
            o.y = acc[d + 1] * inv;
            o.z = acc[d + 2] * inv;
            o.w = acc[d + 3] * inv;
            *reinterpret_cast<float4*>(op + d) = o;
        }
    }
}

// ===================== launcher ============================================
extern "C" void kernel_launch(void* const* d_in, const int* in_sizes, int n_in,
                              void* d_out, int out_size)
{
    const float* word   = (const float*)d_in[0];
    const float* img    = (const float*)d_in[1];
    const float* amask  = (const float*)d_in[2];
    const float* attn_w = (const float*)d_in[3];
    const float* attn_b = (const float*)d_in[4];
    const float* proj_w = (const float*)d_in[5];
    const float* proj_b = (const float*)d_in[6];
    const float* uk_w   = (const float*)d_in[7];
    const float* uk_b   = (const float*)d_in[8];
    const float* uv_w   = (const float*)d_in[9];
    const float* uv_b   = (const float*)d_in[10];
    float* out = (float*)d_out;

    void *p_qkv, *p_kimg, *p_vimg, *p_attn, *p_ahi, *p_alo, *p_whi, *p_wlo, *p_phi, *p_plo;
    cudaGetSymbolAddress(&p_qkv,  g_qkv);
    cudaGetSymbolAddress(&p_kimg, g_kimg);
    cudaGetSymbolAddress(&p_vimg, g_vimg);
    cudaGetSymbolAddress(&p_attn, g_attn);
    cudaGetSymbolAddress(&p_ahi,  g_Ahi);
    cudaGetSymbolAddress(&p_alo,  g_Alo);
    cudaGetSymbolAddress(&p_whi,  g_Whi);
    cudaGetSymbolAddress(&p_wlo,  g_Wlo);
    cudaGetSymbolAddress(&p_phi,  g_Phi);
    cudaGetSymbolAddress(&p_plo,  g_Plo);
    float* qkv  = (float*)p_qkv;
    float* kimg = (float*)p_kimg;
    float* vimg = (float*)p_vimg;
    float* attn = (float*)p_attn;
    __nv_bfloat16* Ahi = (__nv_bfloat16*)p_ahi;
    __nv_bfloat16* Alo = (__nv_bfloat16*)p_alo;
    __nv_bfloat16* Whi = (__nv_bfloat16*)p_whi;
    __nv_bfloat16* Wlo = (__nv_bfloat16*)p_wlo;
    __nv_bfloat16* Phi = (__nv_bfloat16*)p_phi;
    __nv_bfloat16* Plo = (__nv_bfloat16*)p_plo;

    cudaFuncSetAttribute(gemm_mma3, cudaFuncAttributeMaxDynamicSharedMemorySize, GEMM_SMEM_B);

    // conversions: activations + weights (transposed)
    {
        int n4 = MROWS * EMBED / 4;
        conv_split<<<(n4 + 255) / 256, 256>>>(word, Ahi, Alo, n4);
    }
    conv_split_T<<<dim3(NQKV / 32, EMBED / 32), dim3(32, 8)>>>(attn_w, Whi, Wlo, EMBED, NQKV);
    conv_split_T<<<dim3(EMBED / 32, EMBED / 32), dim3(32, 8)>>>(proj_w, Phi, Plo, EMBED, EMBED);

    // 1) QKV projection (HMMA bf16x3)
    gemm_mma3<<<dim3(NQKV / 128, (MROWS + 127) / 128), 256, GEMM_SMEM_B>>>(
        Ahi, Alo, Whi, Wlo, attn_b, qkv, MROWS, NQKV);

    // 2) image K/V
    img_kv_kernel<<<1024, 256>>>(img, uk_w, uk_b, uv_w, uv_b, kimg, vimg);

    // 3) attention
    attn_kernel<<<dim3((SEQ + ATT_QB - 1) / ATT_QB, BATCH * HEADS), ATT_QB>>>(
        qkv, kimg, vimg, amask, attn);

    // 4) convert attention output, then output projection (HMMA bf16x3)
    {
        int n4 = MROWS * EMBED / 4;
        conv_split<<<(n4 + 255) / 256, 256>>>(attn, Ahi, Alo, n4);
    }
    gemm_mma3<<<dim3(EMBED / 128, (MROWS + 127) / 128), 256, GEMM_SMEM_B>>>(
        Ahi, Alo, Phi, Plo, proj_b, out, MROWS, EMBED);
}

// round 4
// speedup vs baseline: 2.6541x; 1.7824x over previous
#include <cuda_runtime.h>
#include <cuda_bf16.h>
#include <cstdint>

#define EMBED 1024
#define HEADS 16
#define HDIM  64
#define BATCH 4
#define SEQ   1023
#define MROWS (BATCH*SEQ)      /* 4092 */
#define NQKV  (3*EMBED)        /* 3072 */

// ===================== scratch (static device globals) =====================
__device__ float g_qkv [BATCH*SEQ*NQKV];      // 50.3 MB
__device__ float g_kimg[BATCH*EMBED];
__device__ float g_vimg[BATCH*EMBED];
__device__ __nv_bfloat16 g_Ahi[4096*1024];    // split activations (reused)
__device__ __nv_bfloat16 g_Alo[4096*1024];
__device__ __nv_bfloat16 g_Whi[NQKV*EMBED];   // qkv weight, transposed [N][K]
__device__ __nv_bfloat16 g_Wlo[NQKV*EMBED];
__device__ __nv_bfloat16 g_Phi[EMBED*EMBED];  // proj weight, transposed
__device__ __nv_bfloat16 g_Plo[EMBED*EMBED];

// ===================== small helpers =======================================
__device__ __forceinline__ uint32_t smem_to_u32(const void* p) {
    uint32_t a;
    asm("{ .reg .u64 t; cvta.to.shared.u64 t, %1; cvt.u32.u64 %0, t; }" : "=r"(a) : "l"(p));
    return a;
}
__device__ __forceinline__ void ldsm4(uint32_t (&r)[4], uint32_t addr) {
    asm volatile("ldmatrix.sync.aligned.m8n8.x4.shared.b16 {%0,%1,%2,%3}, [%4];"
        : "=r"(r[0]), "=r"(r[1]), "=r"(r[2]), "=r"(r[3]) : "r"(addr));
}
__device__ __forceinline__ void ldsm4t(uint32_t (&r)[4], uint32_t addr) {
    asm volatile("ldmatrix.sync.aligned.m8n8.x4.trans.shared.b16 {%0,%1,%2,%3}, [%4];"
        : "=r"(r[0]), "=r"(r[1]), "=r"(r[2]), "=r"(r[3]) : "r"(addr));
}
__device__ __forceinline__ void mma16816(float (&c)[4], const uint32_t (&a)[4],
                                         uint32_t b0, uint32_t b1) {
    asm volatile("mma.sync.aligned.m16n8k16.row.col.f32.bf16.bf16.f32 "
        "{%0,%1,%2,%3}, {%4,%5,%6,%7}, {%8,%9}, {%0,%1,%2,%3};"
        : "+f"(c[0]), "+f"(c[1]), "+f"(c[2]), "+f"(c[3])
        : "r"(a[0]), "r"(a[1]), "r"(a[2]), "r"(a[3]), "r"(b0), "r"(b1));
}
// pack two f32 -> bf16x2 reg: lo half = first arg, hi half = second
__device__ __forceinline__ uint32_t pack_bf16(float lo, float hi) {
    uint32_t r;
    asm("cvt.rn.bf16x2.f32 %0, %1, %2;" : "=r"(r) : "f"(hi), "f"(lo));
    return r;
}

// ===================== conversion kernels ==================================
__global__ __launch_bounds__(256)
void conv_split(const float* __restrict__ in, __nv_bfloat16* __restrict__ hi,
                __nv_bfloat16* __restrict__ lo, int n4)
{
    int i = blockIdx.x * blockDim.x + threadIdx.x;
    if (i >= n4) return;
    float4 v = reinterpret_cast<const float4*>(in)[i];
    __nv_bfloat16 hx = __float2bfloat16_rn(v.x);
    __nv_bfloat16 hy = __float2bfloat16_rn(v.y);
    __nv_bfloat16 hz = __float2bfloat16_rn(v.z);
    __nv_bfloat16 hw = __float2bfloat16_rn(v.w);
    __nv_bfloat162* h2 = reinterpret_cast<__nv_bfloat162*>(hi) + i * 2;
    __nv_bfloat162* l2 = reinterpret_cast<__nv_bfloat162*>(lo) + i * 2;
    h2[0] = __nv_bfloat162(hx, hy);
    h2[1] = __nv_bfloat162(hz, hw);
    l2[0] = __nv_bfloat162(__float2bfloat16_rn(v.x - __bfloat162float(hx)),
                           __float2bfloat16_rn(v.y - __bfloat162float(hy)));
    l2[1] = __nv_bfloat162(__float2bfloat16_rn(v.z - __bfloat162float(hz)),
                           __float2bfloat16_rn(v.w - __bfloat162float(hw)));
}

// fp32 W[K][N] row-major -> bf16 split, transposed: out[n][k]
__global__ __launch_bounds__(256)
void conv_split_T(const float* __restrict__ W, __nv_bfloat16* __restrict__ hi,
                  __nv_bfloat16* __restrict__ lo, int K, int N)
{
    __shared__ float t[32][33];
    int n0 = blockIdx.x * 32, k0 = blockIdx.y * 32;
    int tx = threadIdx.x, ty = threadIdx.y;      // block (32, 8)
    #pragma unroll
    for (int i = 0; i < 32; i += 8)
        t[ty + i][tx] = W[(size_t)(k0 + ty + i) * N + n0 + tx];
    __syncthreads();
    #pragma unroll
    for (int i = 0; i < 32; i += 8) {
        float v = t[tx][ty + i];
        __nv_bfloat16 h = __float2bfloat16_rn(v);
        size_t o = (size_t)(n0 + ty + i) * K + k0 + tx;
        hi[o] = h;
        lo[o] = __float2bfloat16_rn(v - __bfloat162float(h));
    }
}

// ===================== HMMA bf16x3 GEMM ====================================
#define BKC    32
#define NCHU   (EMBED / BKC)          /* 32 */
#define TPAD   40
#define TILE_E (128 * TPAD)
#define STAGE_B (4 * TILE_E * 2)
#define GEMM_SMEM_B (2 * STAGE_B)

__global__ __launch_bounds__(256, 2)
void gemm_mma3(const __nv_bfloat16* __restrict__ Ahi, const __nv_bfloat16* __restrict__ Alo,
               const __nv_bfloat16* __restrict__ Bhi, const __nv_bfloat16* __restrict__ Blo,
               const float* __restrict__ bias, float* __restrict__ C, int M, int N)
{
    extern __shared__ __nv_bfloat16 sm[];
    const uint32_t smb = smem_to_u32(sm);
    const int tid  = threadIdx.x;
    const int wid  = tid >> 5, lane = tid & 31;
    const int wm   = wid & 3,  wn   = wid >> 2;
    const int rowBase = blockIdx.y * 128, colBase = blockIdx.x * 128;

    const int lr = tid >> 2;
    const int lk = (tid & 3) * 8;
    const __nv_bfloat16* gsrc[4];
    gsrc[0] = Ahi + (size_t)(rowBase + lr) * EMBED + lk;
    gsrc[1] = Alo + (size_t)(rowBase + lr) * EMBED + lk;
    gsrc[2] = Bhi + (size_t)(colBase + lr) * EMBED + lk;
    gsrc[3] = Blo + (size_t)(colBase + lr) * EMBED + lk;
    const uint32_t sdst0 = smb + (uint32_t)(lr * TPAD + lk) * 2;

    auto issue = [&](int ch) {
        const uint32_t sb = sdst0 + (uint32_t)(ch & 1) * STAGE_B;
        #pragma unroll
        for (int w = 0; w < 4; w++) {
            const __nv_bfloat16* g = gsrc[w] + ch * BKC;
            const uint32_t d = sb + (uint32_t)w * (TILE_E * 2);
            asm volatile("cp.async.cg.shared.global [%0], [%1], 16;" :: "r"(d), "l"(g));
            asm volatile("cp.async.cg.shared.global [%0], [%1], 16;"
                         :: "r"(d + 64 * TPAD * 2), "l"(g + (size_t)64 * EMBED));
        }
        asm volatile("cp.async.commit_group;");
    };

    float acc[2][8][4] = {};
    const int lrow  = lane & 15;
    const int lcol8 = (lane >> 4) * 8;

    issue(0);
    for (int ch = 0; ch < NCHU; ch++) {
        const int s = ch & 1;
        if (ch + 1 < NCHU) { issue(ch + 1); asm volatile("cp.async.wait_group 1;"); }
        else               { asm volatile("cp.async.wait_group 0;"); }
        __syncthreads();

        const uint32_t stb  = smb + (uint32_t)s * STAGE_B;
        const uint32_t aoff = stb + (uint32_t)((wm * 32 + lrow) * TPAD + lcol8) * 2;
        const uint32_t boff = stb + 2u * (TILE_E * 2)
                            + (uint32_t)((wn * 64 + lrow) * TPAD + lcol8) * 2;
        #pragma unroll
        for (int kk = 0; kk < BKC; kk += 16) {
            uint32_t ah[2][4], al[2][4];
            #pragma unroll
            for (int mt = 0; mt < 2; mt++) {
                ldsm4(ah[mt], aoff + (uint32_t)(mt * 16 * TPAD + kk) * 2);
                ldsm4(al[mt], aoff + (TILE_E * 2) + (uint32_t)(mt * 16 * TPAD + kk) * 2);
            }
            #pragma unroll
            for (int np = 0; np < 4; np++) {
                uint32_t bh[4], bl[4];
                ldsm4(bh, boff + (uint32_t)(np * 16 * TPAD + kk) * 2);
                ldsm4(bl, boff + (TILE_E * 2) + (uint32_t)(np * 16 * TPAD + kk) * 2);
                #pragma unroll
                for (int mt = 0; mt < 2; mt++) {
                    mma16816(acc[mt][np * 2 + 0], ah[mt], bh[0], bh[2]);
                    mma16816(acc[mt][np * 2 + 1], ah[mt], bh[1], bh[3]);
                    mma16816(acc[mt][np * 2 + 0], ah[mt], bl[0], bl[2]);
                    mma16816(acc[mt][np * 2 + 1], ah[mt], bl[1], bl[3]);
                    mma16816(acc[mt][np * 2 + 0], al[mt], bh[0], bh[2]);
                    mma16816(acc[mt][np * 2 + 1], al[mt], bh[1], bh[3]);
                }
            }
        }
        __syncthreads();
    }

    const int erow = lane >> 2;
    const int ecol = (lane & 3) * 2;
    #pragma unroll
    for (int mt = 0; mt < 2; mt++) {
        #pragma unroll
        for (int nt = 0; nt < 8; nt++) {
            const int col = colBase + wn * 64 + nt * 8 + ecol;
            const float bx = bias[col], by = bias[col + 1];
            const int r0 = rowBase + wm * 32 + mt * 16 + erow;
            if (r0 < M) {
                float2 v; v.x = acc[mt][nt][0] + bx; v.y = acc[mt][nt][1] + by;
                *reinterpret_cast<float2*>(&C[(size_t)r0 * N + col]) = v;
            }
            const int r1 = r0 + 8;
            if (r1 < M) {
                float2 v; v.x = acc[mt][nt][2] + bx; v.y = acc[mt][nt][3] + by;
                *reinterpret_cast<float2*>(&C[(size_t)r1 * N + col]) = v;
            }
        }
    }
}

// ===================== image K/V GEMV ======================================
__global__ __launch_bounds__(256)
void img_kv_kernel(const float* __restrict__ img,
                   const float* __restrict__ uk_w, const float* __restrict__ uk_b,
                   const float* __restrict__ uv_w, const float* __restrict__ uv_b,
                   float* __restrict__ kimg, float* __restrict__ vimg)
{
    const int w    = (blockIdx.x * blockDim.x + threadIdx.x) >> 5;
    const int lane = threadIdx.x & 31;
    const int which = w >> 12;
    const int rem   = w & 4095;
    const int b     = rem >> 10;
    const int n     = rem & 1023;

    const float* W    = which ? uv_w : uk_w;
    const float* bias = which ? uv_b : uk_b;
    const float* x    = img + b * EMBED;
    const float* wr   = W + (size_t)n * EMBED;

    float s = 0.f;
    #pragma unroll 4
    for (int e = lane * 4; e < EMBED; e += 128) {
        float4 xv = *reinterpret_cast<const float4*>(x + e);
        float4 wv = *reinterpret_cast<const float4*>(wr + e);
        s += xv.x * wv.x + xv.y * wv.y + xv.z * wv.z + xv.w * wv.w;
    }
    #pragma unroll
    for (int o = 16; o; o >>= 1) s += __shfl_xor_sync(0xffffffffu, s, o);
    if (lane == 0) {
        const float v = s + bias[n];
        if (which) vimg[b * EMBED + n] = v;
        else       kimg[b * EMBED + n] = v;
    }
}

// ===================== HMMA flash attention ================================
// 8 warps, each m16 q-rows; block = 128 queries; key tiles of 64.
// keys: kj=0 -> image K/V; kj>=1 -> word key kj-1; visible iff kj <= qi+1.
// Output written as split bf16 (hi/lo) directly into GEMM2's A buffers.
#define ATPAD 72                       /* 64 + 8 pad: 144B rows, ldsm conflict-free */
#define AQH_B 0
#define AQL_B (128 * ATPAD * 2)        /* 18432 */
#define AKH_B (2 * AQL_B)              /* 36864 */
#define AKL_B (AKH_B + 64 * ATPAD * 2) /* 46080 */
#define AVH_B (AKL_B + 64 * ATPAD * 2) /* 55296 */
#define AVL_B (AVH_B + 64 * ATPAD * 2) /* 64512 */
#define AMS_B (AVL_B + 64 * ATPAD * 2) /* 73728 */
#define ATT_SMEM (AMS_B + 64 * 4)      /* 73984 */

__global__ __launch_bounds__(256)
void attn_mma(const float* __restrict__ qkv,
              const float* __restrict__ kimg, const float* __restrict__ vimg,
              const float* __restrict__ mask,
              __nv_bfloat16* __restrict__ outHi, __nv_bfloat16* __restrict__ outLo)
{
    extern __shared__ __nv_bfloat16 sm[];
    const uint32_t smb = smem_to_u32(sm);
    float* Ms = reinterpret_cast<float*>(reinterpret_cast<char*>(sm) + AMS_B);

    const int bh = blockIdx.y;
    const int b  = bh >> 4;
    const int h  = bh & 15;
    const int q0 = blockIdx.x * 128;
    const int tid = threadIdx.x;
    const int wid = tid >> 5, lane = tid & 31;

    // ---- stage Q (fp32 -> scaled bf16 hi/lo) ----
    {
        const int row = tid >> 1;
        const int d0  = (tid & 1) * 32;
        const int qi  = min(q0 + row, SEQ - 1);
        const float* src = qkv + (size_t)(b * SEQ + qi) * NQKV + h * HDIM + d0;
        __nv_bfloat16* qh = sm + row * ATPAD + d0;
        __nv_bfloat16* ql = qh + (AQL_B / 2);
        #pragma unroll
        for (int j = 0; j < 8; j++) {
            float4 v = *reinterpret_cast<const float4*>(src + j * 4);
            float f[4] = {v.x * 0.125f, v.y * 0.125f, v.z * 0.125f, v.w * 0.125f};
            #pragma unroll
            for (int e = 0; e < 4; e++) {
                __nv_bfloat16 hb = __float2bfloat16_rn(f[e]);
                qh[j * 4 + e] = hb;
                ql[j * 4 + e] = __float2bfloat16_rn(f[e] - __bfloat162float(hb));
            }
        }
    }
    __syncthreads();

    // ---- preload Q fragments ----
    uint32_t qh[4][4], ql[4][4];
    {
        const uint32_t qb = smb + (uint32_t)((wid * 16 + (lane & 15)) * ATPAD + 8 * (lane >> 4)) * 2;
        #pragma unroll
        for (int ks = 0; ks < 4; ks++) {
            ldsm4(qh[ks], qb + ks * 32);
            ldsm4(ql[ks], qb + AQL_B + ks * 32);
        }
    }

    float o[8][4] = {};
    float m0 = -1e30f, m1 = -1e30f, l0 = 0.f, l1 = 0.f;
    const int qi0 = q0 + wid * 16 + (lane >> 2);
    const int qi1 = qi0 + 8;
    const int ccol = 2 * (lane & 3);

    const int q_end  = min(q0 + 128, SEQ) - 1;
    const int kcount = q_end + 2;
    const int ktiles = (kcount + 63) >> 6;

    for (int kt = 0; kt < ktiles; kt++) {
        const int kt0 = kt * 64;
        __syncthreads();
        // ---- load K/V tile (fp32 -> bf16 hi/lo) + mask ----
        {
            const int r  = tid >> 2;
            const int d0 = (tid & 3) * 16;
            const int kj = kt0 + r;
            const float *ksrc, *vsrc;
            if (kj == 0) {
                ksrc = kimg + b * EMBED + h * HDIM + d0;
                vsrc = vimg + b * EMBED + h * HDIM + d0;
            } else {
                const int jj = kj - 1;
                ksrc = qkv + (size_t)(b * SEQ + jj) * NQKV + EMBED + h * HDIM + d0;
                vsrc = ksrc + EMBED;
            }
            __nv_bfloat16* kh = reinterpret_cast<__nv_bfloat16*>(
                reinterpret_cast<char*>(sm) + AKH_B) + r * ATPAD + d0;
            __nv_bfloat16* vh = reinterpret_cast<__nv_bfloat16*>(
                reinterpret_cast<char*>(sm) + AVH_B) + r * ATPAD + d0;
            const int dEl = 64 * ATPAD;   // hi -> lo array distance (elems)
            #pragma unroll
            for (int j = 0; j < 4; j++) {
                float4 kv = *reinterpret_cast<const float4*>(ksrc + j * 4);
                float4 vv = *reinterpret_cast<const float4*>(vsrc + j * 4);
                float kf[4] = {kv.x, kv.y, kv.z, kv.w};
                float vf[4] = {vv.x, vv.y, vv.z, vv.w};
                #pragma unroll
                for (int e = 0; e < 4; e++) {
                    __nv_bfloat16 hb = __float2bfloat16_rn(kf[e]);
                    kh[j * 4 + e] = hb;
                    kh[dEl + j * 4 + e] = __float2bfloat16_rn(kf[e] - __bfloat162float(hb));
                    __nv_bfloat16 hv = __float2bfloat16_rn(vf[e]);
                    vh[j * 4 + e] = hv;
                    vh[dEl + j * 4 + e] = __float2bfloat16_rn(vf[e] - __bfloat162float(hv));
                }
            }
            if (tid < 64) {
                const int kj2 = kt0 + tid;
                Ms[tid] = (kj2 >= 1 && kj2 <= SEQ) ? mask[b * SEQ + kj2 - 1] : 0.f;
            }
        }
        __syncthreads();

        // ---- S = Q @ K^T (3-pass bf16x3) ----
        float sc[8][4];
        #pragma unroll
        for (int i = 0; i < 8; i++)
            #pragma unroll
            for (int j = 0; j < 4; j++) sc[i][j] = 0.f;

        const uint32_t kbh = smb + AKH_B + (uint32_t)((lane & 15) * ATPAD + 8 * (lane >> 4)) * 2;
        #pragma unroll
        for (int ks = 0; ks < 4; ks++) {
            #pragma unroll
            for (int ng = 0; ng < 4; ng++) {
                uint32_t kh4[4], kl4[4];
                const uint32_t ofs = (uint32_t)(ng * 16 * ATPAD) * 2 + ks * 32;
                ldsm4(kh4, kbh + ofs);
                ldsm4(kl4, kbh + (AKL_B - AKH_B) + ofs);
                mma16816(sc[2 * ng + 0], qh[ks], kh4[0], kh4[2]);
                mma16816(sc[2 * ng + 1], qh[ks], kh4[1], kh4[3]);
                mma16816(sc[2 * ng + 0], qh[ks], kl4[0], kl4[2]);
                mma16816(sc[2 * ng + 1], qh[ks], kl4[1], kl4[3]);
                mma16816(sc[2 * ng + 0], ql[ks], kh4[0], kh4[2]);
                mma16816(sc[2 * ng + 1], ql[ks], kh4[1], kh4[3]);
            }
        }

        // ---- mask + causal + online softmax ----
        float mx0 = -1e30f, mx1 = -1e30f;
        #pragma unroll
        for (int nt = 0; nt < 8; nt++) {
            const int col = kt0 + nt * 8 + ccol;
            const float mk0 = Ms[nt * 8 + ccol];
            const float mk1 = Ms[nt * 8 + ccol + 1];
            float s;
            s = sc[nt][0] + mk0; if (col     > qi0 + 1) s = -1e30f; sc[nt][0] = s; mx0 = fmaxf(mx0, s);
            s = sc[nt][1] + mk1; if (col + 1 > qi0 + 1) s = -1e30f; sc[nt][1] = s; mx0 = fmaxf(mx0, s);
            s = sc[nt][2] + mk0; if (col     > qi1 + 1) s = -1e30f; sc[nt][2] = s; mx1 = fmaxf(mx1, s);
            s = sc[nt][3] + mk1; if (col + 1 > qi1 + 1) s = -1e30f; sc[nt][3] = s; mx1 = fmaxf(mx1, s);
        }
        #pragma unroll
        for (int d = 1; d <= 2; d <<= 1) {
            mx0 = fmaxf(mx0, __shfl_xor_sync(0xffffffffu, mx0, d));
            mx1 = fmaxf(mx1, __shfl_xor_sync(0xffffffffu, mx1, d));
        }
        const float mn0 = fmaxf(m0, mx0), mn1 = fmaxf(m1, mx1);
        const float a0 = __expf(m0 - mn0), a1 = __expf(m1 - mn1);
        m0 = mn0; m1 = mn1;
        l0 *= a0; l1 *= a1;
        #pragma unroll
        for (int nt = 0; nt < 8; nt++) {
            o[nt][0] *= a0; o[nt][1] *= a0;
            o[nt][2] *= a1; o[nt][3] *= a1;
        }
        #pragma unroll
        for (int nt = 0; nt < 8; nt++) {
            float p0 = __expf(sc[nt][0] - m0);
            float p1 = __expf(sc[nt][1] - m0);
            float p2 = __expf(sc[nt][2] - m1);
            float p3 = __expf(sc[nt][3] - m1);
            l0 += p0 + p1; l1 += p2 + p3;
            sc[nt][0] = p0; sc[nt][1] = p1; sc[nt][2] = p2; sc[nt][3] = p3;
        }

        // ---- O += P @ V (3-pass) ----
        const uint32_t vbh = smb + AVH_B +
            (uint32_t)(((lane & 7) + 8 * ((lane >> 3) & 1)) * ATPAD + 8 * (lane >> 4)) * 2;
        #pragma unroll
        for (int ks = 0; ks < 4; ks++) {
            // build P A-frags (hi + lo) from S tiles 2ks, 2ks+1
            uint32_t ahi[4], alo[4];
            #pragma unroll
            for (int half = 0; half < 2; half++) {
                const int t = 2 * ks + half;
                float p0 = sc[t][0], p1 = sc[t][1], p2 = sc[t][2], p3 = sc[t][3];
                float h0 = __bfloat162float(__float2bfloat16_rn(p0));
                float h1 = __bfloat162float(__float2bfloat16_rn(p1));
                float h2 = __bfloat162float(__float2bfloat16_rn(p2));
                float h3 = __bfloat162float(__float2bfloat16_rn(p3));
                ahi[2 * half + 0] = pack_bf16(h0, h1);
                ahi[2 * half + 1] = pack_bf16(h2, h3);
                alo[2 * half + 0] = pack_bf16(p0 - h0, p1 - h1);
                alo[2 * half + 1] = pack_bf16(p2 - h2, p3 - h3);
            }
            const uint32_t vkb = vbh + (uint32_t)(ks * 16 * ATPAD) * 2;
            #pragma unroll
            for (int dg = 0; dg < 4; dg++) {
                uint32_t vh4[4], vl4[4];
                ldsm4t(vh4, vkb + dg * 32);
                ldsm4t(vl4, vkb + (AVL_B - AVH_B) + dg * 32);
                mma16816(o[2 * dg + 0], ahi, vh4[0], vh4[1]);
                mma16816(o[2 * dg + 1], ahi, vh4[2], vh4[3]);
                mma16816(o[2 * dg + 0], ahi, vl4[0], vl4[1]);
                mma16816(o[2 * dg + 1], ahi, vl4[2], vl4[3]);
                mma16816(o[2 * dg + 0], alo, vh4[0], vh4[1]);
                mma16816(o[2 * dg + 1], alo, vh4[2], vh4[3]);
            }
        }
    }

    // ---- finalize: normalize + split-write ----
    #pragma unroll
    for (int d = 1; d <= 2; d <<= 1) {
        l0 += __shfl_xor_sync(0xffffffffu, l0, d);
        l1 += __shfl_xor_sync(0xffffffffu, l1, d);
    }
    const float inv0 = 1.f / l0, inv1 = 1.f / l1;
    #pragma unroll
    for (int nt = 0; nt < 8; nt++) {
        const int dcol = nt * 8 + ccol;
        if (qi0 < SEQ) {
            const size_t idx = (size_t)(b * SEQ + qi0) * EMBED + h * HDIM + dcol;
            float f0 = o[nt][0] * inv0, f1 = o[nt][1] * inv0;
            __nv_bfloat16 h0 = __float2bfloat16_rn(f0), h1 = __float2bfloat16_rn(f1);
            *reinterpret_cast<__nv_bfloat162*>(&outHi[idx]) = __nv_bfloat162(h0, h1);
            *reinterpret_cast<__nv_bfloat162*>(&outLo[idx]) = __nv_bfloat162(
                __float2bfloat16_rn(f0 - __bfloat162float(h0)),
                __float2bfloat16_rn(f1 - __bfloat162float(h1)));
        }
        if (qi1 < SEQ) {
            const size_t idx = (size_t)(b * SEQ + qi1) * EMBED + h * HDIM + dcol;
            float f2 = o[nt][2] * inv1, f3 = o[nt][3] * inv1;
            __nv_bfloat16 h2 = __float2bfloat16_rn(f2), h3 = __float2bfloat16_rn(f3);
            *reinterpret_cast<__nv_bfloat162*>(&outHi[idx]) = __nv_bfloat162(h2, h3);
            *reinterpret_cast<__nv_bfloat162*>(&outLo[idx]) = __nv_bfloat162(
                __float2bfloat16_rn(f2 - __bfloat162float(h2)),
                __float2bfloat16_rn(f3 - __bfloat162float(h3)));
        }
    }
}

// ===================== launcher ============================================
extern "C" void kernel_launch(void* const* d_in, const int* in_sizes, int n_in,
                              void* d_out, int out_size)
{
    const float* word   = (const float*)d_in[0];
    const float* img    = (const float*)d_in[1];
    const float* amask  = (const float*)d_in[2];
    const float* attn_w = (const float*)d_in[3];
    const float* attn_b = (const float*)d_in[4];
    const float* proj_w = (const float*)d_in[5];
    const float* proj_b = (const float*)d_in[6];
    const float* uk_w   = (const float*)d_in[7];
    const float* uk_b   = (const float*)d_in[8];
    const float* uv_w   = (const float*)d_in[9];
    const float* uv_b   = (const float*)d_in[10];
    float* out = (float*)d_out;

    void *p_qkv, *p_kimg, *p_vimg, *p_ahi, *p_alo, *p_whi, *p_wlo, *p_phi, *p_plo;
    cudaGetSymbolAddress(&p_qkv,  g_qkv);
    cudaGetSymbolAddress(&p_kimg, g_kimg);
    cudaGetSymbolAddress(&p_vimg, g_vimg);
    cudaGetSymbolAddress(&p_ahi,  g_Ahi);
    cudaGetSymbolAddress(&p_alo,  g_Alo);
    cudaGetSymbolAddress(&p_whi,  g_Whi);
    cudaGetSymbolAddress(&p_wlo,  g_Wlo);
    cudaGetSymbolAddress(&p_phi,  g_Phi);
    cudaGetSymbolAddress(&p_plo,  g_Plo);
    float* qkv  = (float*)p_qkv;
    float* kimg = (float*)p_kimg;
    float* vimg = (float*)p_vimg;
    __nv_bfloat16* Ahi = (__nv_bfloat16*)p_ahi;
    __nv_bfloat16* Alo = (__nv_bfloat16*)p_alo;
    __nv_bfloat16* Whi = (__nv_bfloat16*)p_whi;
    __nv_bfloat16* Wlo = (__nv_bfloat16*)p_wlo;
    __nv_bfloat16* Phi = (__nv_bfloat16*)p_phi;
    __nv_bfloat16* Plo = (__nv_bfloat16*)p_plo;

    cudaFuncSetAttribute(gemm_mma3, cudaFuncAttributeMaxDynamicSharedMemorySize, GEMM_SMEM_B);
    cudaFuncSetAttribute(attn_mma,  cudaFuncAttributeMaxDynamicSharedMemorySize, ATT_SMEM);

    // conversions: word activations + both weights (transposed)
    {
        int n4 = MROWS * EMBED / 4;
        conv_split<<<(n4 + 255) / 256, 256>>>(word, Ahi, Alo, n4);
    }
    conv_split_T<<<dim3(NQKV / 32, EMBED / 32), dim3(32, 8)>>>(attn_w, Whi, Wlo, EMBED, NQKV);
    conv_split_T<<<dim3(EMBED / 32, EMBED / 32), dim3(32, 8)>>>(proj_w, Phi, Plo, EMBED, EMBED);

    // 1) QKV projection (HMMA bf16x3)
    gemm_mma3<<<dim3(NQKV / 128, (MROWS + 127) / 128), 256, GEMM_SMEM_B>>>(
        Ahi, Alo, Whi, Wlo, attn_b, qkv, MROWS, NQKV);

    // 2) image K/V
    img_kv_kernel<<<1024, 256>>>(img, uk_w, uk_b, uv_w, uv_b, kimg, vimg);

    // 3) attention (HMMA, writes split bf16 directly into GEMM2 A-buffers)
    attn_mma<<<dim3(8, BATCH * HEADS), 256, ATT_SMEM>>>(qkv, kimg, vimg, amask, Ahi, Alo);

    // 4) output projection (HMMA bf16x3)
    gemm_mma3<<<dim3(EMBED / 128, (MROWS + 127) / 128), 256, GEMM_SMEM_B>>>(
        Ahi, Alo, Phi, Plo, proj_b, out, MROWS, EMBED);
}